// round 5
// baseline (speedup 1.0000x reference)
#include <cuda_runtime.h>
#include <cstdint>

// FeatureSim: attn[b,i,j] = softmax_j( masked(-sum_f |x[b,i,f]-x[b,j,f]| * w[f]) )
// B=8, N=1024, D=64, NF=11.
// Kernel 1: compact x[:,:,:11] -> (B,N,12) scratch.
// Kernel 2: R=4 rows/CTA, j-rows truly register-cached (launch_bounds(256,2) -> 128 regs),
//           softmax WITHOUT max-pass (scores bounded, exp-safe; invalid j underflows to 0).
// (Third submission of this source — rounds 3 and 4 both died on container
//  acquisition infra failures; the kernel has not yet been measured.)

static constexpr int B_ = 8;
static constexpr int N_ = 1024;
static constexpr int D_ = 64;
static constexpr int NF = 11;
static constexpr int RPAD = 12;
static constexpr int R = 4;
#define BDIM 256

__device__ float g_xc[B_ * N_ * RPAD];   // 384 KB scratch

__global__ void compact_kernel(const float* __restrict__ x) {
    int idx = blockIdx.x * blockDim.x + threadIdx.x;     // 0 .. B*N*3
    if (idx >= B_ * N_ * 3) return;
    int row = idx / 3;
    int q   = idx - row * 3;
    float4 v = *reinterpret_cast<const float4*>(x + (size_t)row * D_ + q * 4);
    *reinterpret_cast<float4*>(g_xc + row * RPAD + q * 4) = v;
}

__global__ __launch_bounds__(BDIM, 2) void featuresim_kernel(
    const int*   __restrict__ xlen,     // (B,)
    const float* __restrict__ fimp,     // (NF,)
    float*       __restrict__ out)      // (B,N,N)
{
    const int b    = blockIdx.y;
    const int i0   = blockIdx.x * R;
    const int tid  = threadIdx.x;
    const int lane = tid & 31;
    const int wid  = tid >> 5;

    const float* xcb = g_xc + b * N_ * RPAD;
    const int len = xlen[b];

    float w[NF];
#pragma unroll
    for (int f = 0; f < NF; f++) w[f] = __ldg(fimp + f);

    // Register-cache this thread's 4 contiguous j-rows: 12 x LDG.128, 192B coalesced.
    const int j0 = tid * 4;
    float rj[4][12];
#pragma unroll
    for (int q = 0; q < 4; q++) {
        const float4* p = reinterpret_cast<const float4*>(xcb + (j0 + q) * RPAD);
        float4 a = p[0], bb = p[1], c = p[2];
        rj[q][0] = a.x;  rj[q][1] = a.y;  rj[q][2]  = a.z;  rj[q][3]  = a.w;
        rj[q][4] = bb.x; rj[q][5] = bb.y; rj[q][6]  = bb.z; rj[q][7]  = bb.w;
        rj[q][8] = c.x;  rj[q][9] = c.y;  rj[q][10] = c.z;  rj[q][11] = c.w;
    }

    const bool val0 = (j0 + 0) < len;
    const bool val1 = (j0 + 1) < len;
    const bool val2 = (j0 + 2) < len;
    const bool val3 = (j0 + 3) < len;

    __shared__ float reds[R][8];

    float e[R][4];
#pragma unroll
    for (int r = 0; r < R; r++) {
        // i-row features (uniform across CTA -> broadcast L1 hits)
        float xi[12];
        {
            const float4* p = reinterpret_cast<const float4*>(xcb + (i0 + r) * RPAD);
            float4 a = p[0], bb = p[1], c = p[2];
            xi[0] = a.x;  xi[1] = a.y;  xi[2]  = a.z;  xi[3]  = a.w;
            xi[4] = bb.x; xi[5] = bb.y; xi[6]  = bb.z; xi[7]  = bb.w;
            xi[8] = c.x;  xi[9] = c.y;  xi[10] = c.z;  xi[11] = c.w;
        }

        float s0 = 0.f, s1 = 0.f, s2 = 0.f, s3 = 0.f;
#pragma unroll
        for (int f = 0; f < NF; f++) {
            const float xif = xi[f];
            const float wf  = w[f];
            s0 = fmaf(fabsf(rj[0][f] - xif), wf, s0);
            s1 = fmaf(fabsf(rj[1][f] - xif), wf, s1);
            s2 = fmaf(fabsf(rj[2][f] - xif), wf, s2);
            s3 = fmaf(fabsf(rj[3][f] - xif), wf, s3);
        }
        float t0 = (s0 < 1.0f) ? -s0 : 0.0f;
        float t1 = (s1 < 1.0f) ? -s1 : 0.0f;
        float t2 = (s2 < 1.0f) ? -s2 : 0.0f;
        float t3 = (s3 < 1.0f) ? -s3 : 0.0f;

        // No max-pass: valid scores are small (|t| < ~30), exp is safe;
        // invalid j -> exp(-1e9) underflows to exactly 0.
        e[r][0] = __expf(val0 ? t0 : -1.0e9f);
        e[r][1] = __expf(val1 ? t1 : -1.0e9f);
        e[r][2] = __expf(val2 ? t2 : -1.0e9f);
        e[r][3] = __expf(val3 ? t3 : -1.0e9f);

        float ps = (e[r][0] + e[r][1]) + (e[r][2] + e[r][3]);
#pragma unroll
        for (int o = 16; o > 0; o >>= 1)
            ps += __shfl_xor_sync(0xFFFFFFFFu, ps, o);
        if (lane == 0) reds[r][wid] = ps;
    }
    __syncthreads();

#pragma unroll
    for (int r = 0; r < R; r++) {
        float t = reds[r][0];
#pragma unroll
        for (int k = 1; k < 8; k++) t += reds[r][k];
        const float inv = 1.0f / t;
        float4 o4;
        o4.x = e[r][0] * inv;
        o4.y = e[r][1] * inv;
        o4.z = e[r][2] * inv;
        o4.w = e[r][3] * inv;
        *reinterpret_cast<float4*>(out + ((size_t)(b * N_ + i0 + r)) * N_ + j0) = o4;
    }
}

extern "C" void kernel_launch(void* const* d_in, const int* in_sizes, int n_in,
                              void* d_out, int out_size)
{
    const float* x    = (const float*)d_in[0];
    const int*   xlen = (const int*)d_in[1];
    const float* fimp = (const float*)d_in[2];
    float*       out  = (float*)d_out;

    compact_kernel<<<(B_ * N_ * 3 + BDIM - 1) / BDIM, BDIM>>>(x);
    dim3 grid(N_ / R, B_);
    featuresim_kernel<<<grid, BDIM>>>(xlen, fimp, out);
}

// round 7
// speedup vs baseline: 1.2841x; 1.2841x over previous
#include <cuda_runtime.h>
#include <cstdint>

// FeatureSim: attn[b,i,j] = softmax_j( masked(-sum_f |x[b,i,f]-x[b,j,f]| * w[f]) )
// B=8, N=1024, D=64, NF=11.
// Kernel 1: transpose x[:,:,:11] -> SoA planes g_xt[f][b*N + row]  (coalesced j-loads)
// Kernel 2: R=4 rows/CTA; per-feature float4 j-loads are fully coalesced across lanes;
//           softmax without max-pass (valid scores bounded in (-1,0], exp-safe;
//           invalid j -> exp(-1e9) == 0).
// (Resubmission — round 6 died on container-acquisition infra, source never ran.)

static constexpr int B_ = 8;
static constexpr int N_ = 1024;
static constexpr int D_ = 64;
static constexpr int NF = 11;
static constexpr int BN = B_ * N_;   // 8192
static constexpr int R = 4;
#define BDIM 256

__device__ float g_xt[NF * BN];   // 352 KB scratch, feature-major (SoA)

__global__ void transpose_kernel(const float* __restrict__ x) {
    int row = blockIdx.x * blockDim.x + threadIdx.x;   // 0 .. 8191
    if (row >= BN) return;
    const float4* p = reinterpret_cast<const float4*>(x + (size_t)row * D_);
    float4 a = p[0], b4 = p[1], c = p[2];
    float v[12];
    v[0] = a.x;  v[1] = a.y;  v[2]  = a.z;  v[3]  = a.w;
    v[4] = b4.x; v[5] = b4.y; v[6]  = b4.z; v[7]  = b4.w;
    v[8] = c.x;  v[9] = c.y;  v[10] = c.z;  v[11] = c.w;
#pragma unroll
    for (int f = 0; f < NF; f++)
        g_xt[f * BN + row] = v[f];     // coalesced across threads per plane
}

__global__ __launch_bounds__(BDIM, 2) void featuresim_kernel(
    const int*   __restrict__ xlen,     // (B,)
    const float* __restrict__ fimp,     // (NF,)
    float*       __restrict__ out)      // (B,N,N)
{
    const int b    = blockIdx.y;
    const int i0   = blockIdx.x * R;
    const int tid  = threadIdx.x;
    const int lane = tid & 31;
    const int wid  = tid >> 5;

    const int base = b * N_;
    const int len  = xlen[b];
    const int j0   = tid * 4;

    float w[NF];
#pragma unroll
    for (int f = 0; f < NF; f++) w[f] = __ldg(fimp + f);

    // j-row features, SoA: one float4 per feature, consecutive lanes read
    // consecutive float4s -> fully coalesced LDG.128 (4 wavefronts/warp each).
    float4 rjf[NF];
#pragma unroll
    for (int f = 0; f < NF; f++)
        rjf[f] = *reinterpret_cast<const float4*>(g_xt + f * BN + base + j0);

    const bool val0 = (j0 + 0) < len;
    const bool val1 = (j0 + 1) < len;
    const bool val2 = (j0 + 2) < len;
    const bool val3 = (j0 + 3) < len;

    __shared__ float reds[R][8];

    float e[R][4];
#pragma unroll
    for (int r = 0; r < R; r++) {
        // i-row features: uniform scalar loads (1 broadcast wavefront each)
        float xi[NF];
#pragma unroll
        for (int f = 0; f < NF; f++)
            xi[f] = g_xt[f * BN + base + i0 + r];

        float s0 = 0.f, s1 = 0.f, s2 = 0.f, s3 = 0.f;
#pragma unroll
        for (int f = 0; f < NF; f++) {
            const float xif = xi[f];
            const float wf  = w[f];
            s0 = fmaf(fabsf(rjf[f].x - xif), wf, s0);
            s1 = fmaf(fabsf(rjf[f].y - xif), wf, s1);
            s2 = fmaf(fabsf(rjf[f].z - xif), wf, s2);
            s3 = fmaf(fabsf(rjf[f].w - xif), wf, s3);
        }
        float t0 = (s0 < 1.0f) ? -s0 : 0.0f;
        float t1 = (s1 < 1.0f) ? -s1 : 0.0f;
        float t2 = (s2 < 1.0f) ? -s2 : 0.0f;
        float t3 = (s3 < 1.0f) ? -s3 : 0.0f;

        // No max-pass: valid scores bounded in (-1, 0]; invalid -> exact 0.
        e[r][0] = __expf(val0 ? t0 : -1.0e9f);
        e[r][1] = __expf(val1 ? t1 : -1.0e9f);
        e[r][2] = __expf(val2 ? t2 : -1.0e9f);
        e[r][3] = __expf(val3 ? t3 : -1.0e9f);

        float ps = (e[r][0] + e[r][1]) + (e[r][2] + e[r][3]);
#pragma unroll
        for (int o = 16; o > 0; o >>= 1)
            ps += __shfl_xor_sync(0xFFFFFFFFu, ps, o);
        if (lane == 0) reds[r][wid] = ps;
    }
    __syncthreads();

#pragma unroll
    for (int r = 0; r < R; r++) {
        float t = reds[r][0];
#pragma unroll
        for (int k = 1; k < 8; k++) t += reds[r][k];
        const float inv = 1.0f / t;
        float4 o4;
        o4.x = e[r][0] * inv;
        o4.y = e[r][1] * inv;
        o4.z = e[r][2] * inv;
        o4.w = e[r][3] * inv;
        *reinterpret_cast<float4*>(out + ((size_t)(b * N_ + i0 + r)) * N_ + j0) = o4;
    }
}

extern "C" void kernel_launch(void* const* d_in, const int* in_sizes, int n_in,
                              void* d_out, int out_size)
{
    const float* x    = (const float*)d_in[0];
    const int*   xlen = (const int*)d_in[1];
    const float* fimp = (const float*)d_in[2];
    float*       out  = (float*)d_out;

    transpose_kernel<<<(BN + BDIM - 1) / BDIM, BDIM>>>(x);
    dim3 grid(N_ / R, B_);
    featuresim_kernel<<<grid, BDIM>>>(xlen, fimp, out);
}

// round 8
// speedup vs baseline: 1.3257x; 1.0325x over previous
#include <cuda_runtime.h>
#include <cstdint>

// FeatureSim: attn[b,i,j] = softmax_j( masked(-sum_f |x[b,i,f]-x[b,j,f]| * w[f]) )
// B=8, N=1024, D=64, NF=11.
// Kernel 1: transpose x[:,:,:11] -> SoA planes g_xt[f][b*N + row]  (coalesced j-loads)
// Kernel 2: R=8 rows/CTA (2x reuse of register-cached j-features, 2x ILP to cover
//           MUFU/SHFL latency); softmax without max-pass (valid scores in (-1,0],
//           exp-safe; invalid j -> exp(-1e9) == 0).

static constexpr int B_ = 8;
static constexpr int N_ = 1024;
static constexpr int D_ = 64;
static constexpr int NF = 11;
static constexpr int BN = B_ * N_;   // 8192
static constexpr int R = 8;
#define BDIM 256

__device__ float g_xt[NF * BN];   // 352 KB scratch, feature-major (SoA)

__global__ void transpose_kernel(const float* __restrict__ x) {
    int row = blockIdx.x * blockDim.x + threadIdx.x;   // 0 .. 8191
    if (row >= BN) return;
    const float4* p = reinterpret_cast<const float4*>(x + (size_t)row * D_);
    float4 a = p[0], b4 = p[1], c = p[2];
    float v[12];
    v[0] = a.x;  v[1] = a.y;  v[2]  = a.z;  v[3]  = a.w;
    v[4] = b4.x; v[5] = b4.y; v[6]  = b4.z; v[7]  = b4.w;
    v[8] = c.x;  v[9] = c.y;  v[10] = c.z;  v[11] = c.w;
#pragma unroll
    for (int f = 0; f < NF; f++)
        g_xt[f * BN + row] = v[f];     // coalesced across threads per plane
}

__global__ __launch_bounds__(BDIM, 2) void featuresim_kernel(
    const int*   __restrict__ xlen,     // (B,)
    const float* __restrict__ fimp,     // (NF,)
    float*       __restrict__ out)      // (B,N,N)
{
    const int b    = blockIdx.y;
    const int i0   = blockIdx.x * R;
    const int tid  = threadIdx.x;
    const int lane = tid & 31;
    const int wid  = tid >> 5;

    const int base = b * N_;
    const int len  = xlen[b];
    const int j0   = tid * 4;

    float w[NF];
#pragma unroll
    for (int f = 0; f < NF; f++) w[f] = __ldg(fimp + f);

    // j-row features, SoA: one float4 per feature, consecutive lanes read
    // consecutive float4s -> fully coalesced LDG.128. Reused across all R rows.
    float4 rjf[NF];
#pragma unroll
    for (int f = 0; f < NF; f++)
        rjf[f] = *reinterpret_cast<const float4*>(g_xt + f * BN + base + j0);

    const bool val0 = (j0 + 0) < len;
    const bool val1 = (j0 + 1) < len;
    const bool val2 = (j0 + 2) < len;
    const bool val3 = (j0 + 3) < len;

    __shared__ float reds[R][8];

    float e[R][4];
#pragma unroll
    for (int r = 0; r < R; r++) {
        // i-row features: uniform scalar loads (broadcast L1 hits)
        float xi[NF];
#pragma unroll
        for (int f = 0; f < NF; f++)
            xi[f] = g_xt[f * BN + base + i0 + r];

        float s0 = 0.f, s1 = 0.f, s2 = 0.f, s3 = 0.f;
#pragma unroll
        for (int f = 0; f < NF; f++) {
            const float xif = xi[f];
            const float wf  = w[f];
            s0 = fmaf(fabsf(rjf[f].x - xif), wf, s0);
            s1 = fmaf(fabsf(rjf[f].y - xif), wf, s1);
            s2 = fmaf(fabsf(rjf[f].z - xif), wf, s2);
            s3 = fmaf(fabsf(rjf[f].w - xif), wf, s3);
        }
        float t0 = (s0 < 1.0f) ? -s0 : 0.0f;
        float t1 = (s1 < 1.0f) ? -s1 : 0.0f;
        float t2 = (s2 < 1.0f) ? -s2 : 0.0f;
        float t3 = (s3 < 1.0f) ? -s3 : 0.0f;

        // No max-pass: valid scores bounded in (-1, 0]; invalid -> exact 0.
        e[r][0] = __expf(val0 ? t0 : -1.0e9f);
        e[r][1] = __expf(val1 ? t1 : -1.0e9f);
        e[r][2] = __expf(val2 ? t2 : -1.0e9f);
        e[r][3] = __expf(val3 ? t3 : -1.0e9f);

        float ps = (e[r][0] + e[r][1]) + (e[r][2] + e[r][3]);
#pragma unroll
        for (int o = 16; o > 0; o >>= 1)
            ps += __shfl_xor_sync(0xFFFFFFFFu, ps, o);
        if (lane == 0) reds[r][wid] = ps;
    }
    __syncthreads();

#pragma unroll
    for (int r = 0; r < R; r++) {
        float t = reds[r][0];
#pragma unroll
        for (int k = 1; k < 8; k++) t += reds[r][k];
        const float inv = 1.0f / t;
        float4 o4;
        o4.x = e[r][0] * inv;
        o4.y = e[r][1] * inv;
        o4.z = e[r][2] * inv;
        o4.w = e[r][3] * inv;
        *reinterpret_cast<float4*>(out + ((size_t)(b * N_ + i0 + r)) * N_ + j0) = o4;
    }
}

extern "C" void kernel_launch(void* const* d_in, const int* in_sizes, int n_in,
                              void* d_out, int out_size)
{
    const float* x    = (const float*)d_in[0];
    const int*   xlen = (const int*)d_in[1];
    const float* fimp = (const float*)d_in[2];
    float*       out  = (float*)d_out;

    transpose_kernel<<<(BN + BDIM - 1) / BDIM, BDIM>>>(x);
    dim3 grid(N_ / R, B_);
    featuresim_kernel<<<grid, BDIM>>>(xlen, fimp, out);
}